// round 7
// baseline (speedup 1.0000x reference)
#include <cuda_runtime.h>
#include <cstdint>
#include <math.h>

#define BB 2
#define SS 1024
#define DD 1024
#define HH 16
#define HD 64
#define LL 4
#define VV 32000
#define NROW (BB * SS)   // 2048

// ---------------- scratch (static device globals; no allocs allowed) --------
__device__ float g_x[NROW * DD];
__device__ float g_q[NROW * DD];
__device__ float g_k[NROW * DD];
__device__ float g_v[NROW * DD];
__device__ float g_ctx[NROW * DD];
__device__ float g_attn[NROW * DD];

__device__ __forceinline__ float tf32r(float x) {
    float r; asm("cvt.rna.tf32.f32 %0, %1;" : "=f"(r) : "f"(x)); return r;
}

// =================== tf32 mma.sync GEMM, fragment-major smem ================
// (per-layer kernel: CTA 128x128, BK=32, 2 stages, warp tile 64x32)

#define GEMM_SMEM_FLOATS 16384
#define GEMM_SMEM_BYTES  (GEMM_SMEM_FLOATS * 4)

__device__ __forceinline__ void gemm_core(
    const float* __restrict__ A, const float* __restrict__ W,
    const float* __restrict__ bias, float* __restrict__ C,
    int M, int N, int K, int bm, int bn, float* sm)
{
    const int t    = threadIdx.x;
    const int lane = t & 31;
    const int wid  = t >> 5;
    const int g    = lane >> 2;
    const int tg   = lane & 3;
    const int wm   = (wid & 1) * 64;
    const int wn   = (wid >> 1) * 32;

    float acc[4][4][4];
#pragma unroll
    for (int mf = 0; mf < 4; mf++)
#pragma unroll
        for (int nf = 0; nf < 4; nf++)
#pragma unroll
            for (int r = 0; r < 4; r++) acc[mf][nf][r] = 0.0f;

    int aBase[4], bBase[4];
#pragma unroll
    for (int i = 0; i < 4; i++) {
        int idx = t + i * 256;
        {
            int row = idx >> 3, c4 = idx & 7;
            int mi = row >> 4, m16 = row & 15;
            int ga = m16 & 7, rA = m16 >> 3;
            int ki = c4 >> 1, khi = c4 & 1;
            aBase[i] = ((mi * 4 + ki) * 32) * 4 + (rA + 2 * khi);
            aBase[i] |= (ga << 24) | (ki << 28);
        }
        {
            int rowk = idx >> 5, c4 = idx & 31;
            int n0 = c4 * 4;
            int ki = rowk >> 3, kk = rowk & 7;
            int tgb = kk & 3, hi = kk >> 2;
            int ni = n0 >> 3, g0 = n0 & 7;
            int swz = ((ni & 3) << 3) ^ (((ni >> 2) & 3) << 1);
            int ln0 = g0 * 4 + tgb;
            bBase[i] = ((ni * 4 + ki) * 32) * 2 + hi;
            bBase[i] |= (ln0 << 20) | (swz << 26);
        }
    }

    const int nkt = K >> 5;

    const float* aPtr[4];
    const float* bPtr[4];
#pragma unroll
    for (int i = 0; i < 4; i++) {
        int idx = t + i * 256;
        aPtr[i] = A + (size_t)(bm + (idx >> 3)) * K + (idx & 7) * 4;
        bPtr[i] = W + (size_t)(idx >> 5) * N + bn + (idx & 31) * 4;
    }

    auto storeA = [&](int s, int i, float4 v) {
        int meta = aBase[i];
        int base = meta & 0xFFFFF;
        int ga   = (meta >> 24) & 7;
        int ki   = (meta >> 28) & 3;
        float* dst = sm + s * 4096;
        float vv[4] = {tf32r(v.x), tf32r(v.y), tf32r(v.z), tf32r(v.w)};
#pragma unroll
        for (int e = 0; e < 4; e++) {
            int lp = (ga * 4 + e) ^ ki;
            dst[base + lp * 4] = vv[e];
        }
    };
    auto storeB = [&](int s, int i, float4 v) {
        int meta = bBase[i];
        int base = meta & 0xFFFFF;
        int ln0  = (meta >> 20) & 63;
        int swz  = (meta >> 26) & 31;
        float* dst = sm + 8192 + s * 4096;
        float vv[4] = {tf32r(v.x), tf32r(v.y), tf32r(v.z), tf32r(v.w)};
#pragma unroll
        for (int e = 0; e < 4; e++) {
            int lp = (ln0 + 4 * e) ^ swz;
            dst[base + lp * 2] = vv[e];
        }
    };

#pragma unroll
    for (int i = 0; i < 4; i++) {
        storeA(0, i, *(const float4*)aPtr[i]);
        storeB(0, i, *(const float4*)bPtr[i]);
    }
    __syncthreads();

    int bswz[4];
#pragma unroll
    for (int nf = 0; nf < 4; nf++) {
        int ni = (wid >> 1) * 4 + nf;
        bswz[nf] = lane ^ ((ni & 3) << 3) ^ (((ni >> 2) & 3) << 1);
    }

    for (int kt = 0; kt < nkt; kt++) {
        const int cur = kt & 1;
        float4 pa[4], pb[4];
        const bool pf = (kt + 1 < nkt);
        if (pf) {
            const size_t ko = (size_t)(kt + 1) << 5;
#pragma unroll
            for (int i = 0; i < 4; i++) {
                pa[i] = *(const float4*)(aPtr[i] + ko);
                pb[i] = *(const float4*)(bPtr[i] + ko * (size_t)N);
            }
        }

        const float* asb = sm + cur * 4096;
        const float* bsb = sm + 8192 + cur * 4096;
#pragma unroll
        for (int ki = 0; ki < 4; ki++) {
            float4 afv[4];
            float2 bfv[4];
#pragma unroll
            for (int mf = 0; mf < 4; mf++) {
                int mi = (wid & 1) * 4 + mf;
                afv[mf] = *(const float4*)(asb + ((mi * 4 + ki) * 32 + (lane ^ ki)) * 4);
            }
#pragma unroll
            for (int nf = 0; nf < 4; nf++) {
                int ni = (wid >> 1) * 4 + nf;
                bfv[nf] = *(const float2*)(bsb + ((ni * 4 + ki) * 32 + bswz[nf]) * 2);
            }
#pragma unroll
            for (int mf = 0; mf < 4; mf++)
#pragma unroll
                for (int nf = 0; nf < 4; nf++) {
                    asm volatile(
                        "mma.sync.aligned.m16n8k8.row.col.f32.tf32.tf32.f32 "
                        "{%0,%1,%2,%3}, {%4,%5,%6,%7}, {%8,%9}, {%0,%1,%2,%3};"
                        : "+f"(acc[mf][nf][0]), "+f"(acc[mf][nf][1]),
                          "+f"(acc[mf][nf][2]), "+f"(acc[mf][nf][3])
                        : "r"(__float_as_uint(afv[mf].x)), "r"(__float_as_uint(afv[mf].y)),
                          "r"(__float_as_uint(afv[mf].z)), "r"(__float_as_uint(afv[mf].w)),
                          "r"(__float_as_uint(bfv[nf].x)), "r"(__float_as_uint(bfv[nf].y)));
                }
        }

        if (pf) {
            const int nxt = 1 - cur;
#pragma unroll
            for (int i = 0; i < 4; i++) {
                storeA(nxt, i, pa[i]);
                storeB(nxt, i, pb[i]);
            }
        }
        __syncthreads();
    }

#pragma unroll
    for (int mf = 0; mf < 4; mf++) {
        const int r0 = bm + wm + mf * 16 + g;
        const int r1 = r0 + 8;
#pragma unroll
        for (int nf = 0; nf < 4; nf++) {
            const int col = bn + wn + nf * 8 + tg * 2;
            const float b0 = bias[col], b1 = bias[col + 1];
            float2 v0 = make_float2(acc[mf][nf][0] + b0, acc[mf][nf][1] + b1);
            float2 v1 = make_float2(acc[mf][nf][2] + b0, acc[mf][nf][3] + b1);
            *(float2*)(C + (size_t)r0 * N + col) = v0;
            *(float2*)(C + (size_t)r1 * N + col) = v1;
        }
    }
}

__global__ void __launch_bounds__(256)
gemm_mma(const float* __restrict__ A, const float* __restrict__ W,
         const float* __restrict__ bias, float* __restrict__ C,
         int M, int N, int K)
{
    extern __shared__ float sm[];
    gemm_core(A, W, bias, C, M, N, K, blockIdx.x * 128, blockIdx.y * 128, sm);
}

__global__ void __launch_bounds__(256)
gemm_mma_qkv(const float* __restrict__ A,
             const float* __restrict__ qw, const float* __restrict__ kw,
             const float* __restrict__ vw,
             const float* __restrict__ qb, const float* __restrict__ kb,
             const float* __restrict__ vb,
             float* __restrict__ qo, float* __restrict__ ko, float* __restrict__ vo)
{
    extern __shared__ float sm[];
    const float* W    = (blockIdx.z == 0) ? qw : (blockIdx.z == 1) ? kw : vw;
    const float* bias = (blockIdx.z == 0) ? qb : (blockIdx.z == 1) ? kb : vb;
    float*       C    = (blockIdx.z == 0) ? qo : (blockIdx.z == 1) ? ko : vo;
    gemm_core(A, W, bias, C, NROW, DD, DD, blockIdx.x * 128, blockIdx.y * 128, sm);
}

// =================== big-N GEMM for logits: CTA 128x256, warp 64x64 =========
// BK=16, 2 stages. Fragment-major smem:
//   A stage s at s*2048:      ((mi*2+ki)*32 + (lane^ki))*4 + r          (2048 f)
//   B stage s at 4096+s*4096: ((ni*2+ki)*32 + (lane^swz(ni)))*2 + hi    (4096 f)
//   swz(ni) = ((ni&3)<<3) ^ ((ni>>2)<<1),  ni in 0..31

#define GEMM_BIG_SMEM_FLOATS 12288
#define GEMM_BIG_SMEM_BYTES  (GEMM_BIG_SMEM_FLOATS * 4)

__global__ void __launch_bounds__(256)
gemm_big(const float* __restrict__ A, const float* __restrict__ W,
         const float* __restrict__ bias, float* __restrict__ C,
         int M, int N, int K)
{
    extern __shared__ float sm[];
    const int t    = threadIdx.x;
    const int lane = t & 31;
    const int wid  = t >> 5;
    const int g    = lane >> 2;
    const int tg   = lane & 3;
    const int bm   = blockIdx.x * 128;
    const int bn   = blockIdx.y * 256;
    const int wm   = (wid & 1) * 64;
    const int wn   = (wid >> 1) * 64;

    float acc[4][8][4];
#pragma unroll
    for (int mf = 0; mf < 4; mf++)
#pragma unroll
        for (int nf = 0; nf < 8; nf++)
#pragma unroll
            for (int r = 0; r < 4; r++) acc[mf][nf][r] = 0.0f;

    // A: 128x16 = 512 float4, 2/thread: row=idx>>2, c4=idx&3
    // B: 16x256 = 1024 float4, 4/thread: rowk=idx>>6, c4=idx&63
    int aBase[2], bBase[4];
#pragma unroll
    for (int i = 0; i < 2; i++) {
        int idx = t + i * 256;
        int row = idx >> 2, c4 = idx & 3;
        int mi = row >> 4, m16 = row & 15;
        int ga = m16 & 7, rA = m16 >> 3;
        int ki = c4 >> 1, khi = c4 & 1;
        aBase[i] = ((mi * 2 + ki) * 32) * 4 + (rA + 2 * khi);
        aBase[i] |= (ga << 24) | (ki << 28);
    }
#pragma unroll
    for (int i = 0; i < 4; i++) {
        int idx = t + i * 256;
        int rowk = idx >> 6, c4 = idx & 63;
        int n0 = c4 * 4;
        int ki = rowk >> 3, kk = rowk & 7;
        int tgb = kk & 3, hi = kk >> 2;
        int ni = n0 >> 3, g0 = n0 & 7;
        int swz = ((ni & 3) << 3) ^ ((ni >> 2) << 1);
        int ln0 = g0 * 4 + tgb;
        bBase[i] = ((ni * 2 + ki) * 32) * 2 + hi;
        bBase[i] |= (ln0 << 20) | (swz << 25);
    }

    const float* aPtr[2];
    const float* bPtr[4];
#pragma unroll
    for (int i = 0; i < 2; i++) {
        int idx = t + i * 256;
        aPtr[i] = A + (size_t)(bm + (idx >> 2)) * K + (idx & 3) * 4;
    }
#pragma unroll
    for (int i = 0; i < 4; i++) {
        int idx = t + i * 256;
        bPtr[i] = W + (size_t)(idx >> 6) * N + bn + (idx & 63) * 4;
    }

    auto storeA = [&](int s, int i, float4 v) {
        int meta = aBase[i];
        int base = meta & 0xFFFFF;
        int ga   = (meta >> 24) & 7;
        int ki   = (meta >> 28) & 3;
        float* dst = sm + s * 2048;
        float vv[4] = {tf32r(v.x), tf32r(v.y), tf32r(v.z), tf32r(v.w)};
#pragma unroll
        for (int e = 0; e < 4; e++) {
            int lp = (ga * 4 + e) ^ ki;
            dst[base + lp * 4] = vv[e];
        }
    };
    auto storeB = [&](int s, int i, float4 v) {
        int meta = bBase[i];
        int base = meta & 0xFFFFF;
        int ln0  = (meta >> 20) & 31;
        int swz  = (meta >> 25) & 31;
        float* dst = sm + 4096 + s * 4096;
        float vv[4] = {tf32r(v.x), tf32r(v.y), tf32r(v.z), tf32r(v.w)};
#pragma unroll
        for (int e = 0; e < 4; e++) {
            int lp = (ln0 + 4 * e) ^ swz;
            dst[base + lp * 2] = vv[e];
        }
    };

    const int nkt = K >> 4;

#pragma unroll
    for (int i = 0; i < 2; i++) storeA(0, i, *(const float4*)aPtr[i]);
#pragma unroll
    for (int i = 0; i < 4; i++) storeB(0, i, *(const float4*)bPtr[i]);
    __syncthreads();

    int bswz[8];
#pragma unroll
    for (int nf = 0; nf < 8; nf++) {
        int ni = (wid >> 1) * 8 + nf;
        bswz[nf] = lane ^ (((ni & 3) << 3) ^ ((ni >> 2) << 1));
    }

    for (int kt = 0; kt < nkt; kt++) {
        const int cur = kt & 1;
        float4 pa[2], pb[4];
        const bool pf = (kt + 1 < nkt);
        if (pf) {
            const size_t ko = (size_t)(kt + 1) << 4;
#pragma unroll
            for (int i = 0; i < 2; i++) pa[i] = *(const float4*)(aPtr[i] + ko);
#pragma unroll
            for (int i = 0; i < 4; i++) pb[i] = *(const float4*)(bPtr[i] + ko * (size_t)N);
        }

        const float* asb = sm + cur * 2048;
        const float* bsb = sm + 4096 + cur * 4096;
#pragma unroll
        for (int ki = 0; ki < 2; ki++) {
            float4 afv[4];
            float2 bfv[8];
#pragma unroll
            for (int mf = 0; mf < 4; mf++) {
                int mi = (wid & 1) * 4 + mf;
                afv[mf] = *(const float4*)(asb + ((mi * 2 + ki) * 32 + (lane ^ ki)) * 4);
            }
#pragma unroll
            for (int nf = 0; nf < 8; nf++) {
                int ni = (wid >> 1) * 8 + nf;
                bfv[nf] = *(const float2*)(bsb + ((ni * 2 + ki) * 32 + bswz[nf]) * 2);
            }
#pragma unroll
            for (int mf = 0; mf < 4; mf++)
#pragma unroll
                for (int nf = 0; nf < 8; nf++) {
                    asm volatile(
                        "mma.sync.aligned.m16n8k8.row.col.f32.tf32.tf32.f32 "
                        "{%0,%1,%2,%3}, {%4,%5,%6,%7}, {%8,%9}, {%0,%1,%2,%3};"
                        : "+f"(acc[mf][nf][0]), "+f"(acc[mf][nf][1]),
                          "+f"(acc[mf][nf][2]), "+f"(acc[mf][nf][3])
                        : "r"(__float_as_uint(afv[mf].x)), "r"(__float_as_uint(afv[mf].y)),
                          "r"(__float_as_uint(afv[mf].z)), "r"(__float_as_uint(afv[mf].w)),
                          "r"(__float_as_uint(bfv[nf].x)), "r"(__float_as_uint(bfv[nf].y)));
                }
        }

        if (pf) {
            const int nxt = 1 - cur;
#pragma unroll
            for (int i = 0; i < 2; i++) storeA(nxt, i, pa[i]);
#pragma unroll
            for (int i = 0; i < 4; i++) storeB(nxt, i, pb[i]);
        }
        __syncthreads();
    }

#pragma unroll
    for (int mf = 0; mf < 4; mf++) {
        const int r0 = bm + wm + mf * 16 + g;
        const int r1 = r0 + 8;
#pragma unroll
        for (int nf = 0; nf < 8; nf++) {
            const int col = bn + wn + nf * 8 + tg * 2;
            const float b0 = bias[col], b1 = bias[col + 1];
            float2 v0 = make_float2(acc[mf][nf][0] + b0, acc[mf][nf][1] + b1);
            float2 v1 = make_float2(acc[mf][nf][2] + b0, acc[mf][nf][3] + b1);
            *(float2*)(C + (size_t)r0 * N + col) = v0;
            *(float2*)(C + (size_t)r1 * N + col) = v1;
        }
    }
}

// ---------------- embedding + sinusoidal positional encoding ---------------
__global__ void embed_kernel(const int* __restrict__ tokens,
                             const float* __restrict__ emb,
                             float* __restrict__ x)
{
    int row = blockIdx.x;
    int pos = row & (SS - 1);
    int tok = tokens[row];
    const float* e = emb + (size_t)tok * DD;
    float* xr = x + (size_t)row * DD;
    const float c = -logf(10000.0f) / (float)DD;
    for (int d = threadIdx.x; d < DD; d += blockDim.x) {
        int i = d >> 1;
        float ang = (float)pos * expf((float)(2 * i) * c);
        float pe = (d & 1) ? cosf(ang) : sinf(ang);
        xr[d] = e[d] + pe;
    }
}

// ---------------- causal flash attention, tile-level online softmax --------
__global__ void __launch_bounds__(128)
attn_kernel(const float* __restrict__ Q, const float* __restrict__ K,
            const float* __restrict__ V, float* __restrict__ O)
{
    __shared__ float Ks[32][64];
    __shared__ float Vs[32][64];

    const int b = blockIdx.z;
    const int h = blockIdx.y;
    const int qi = blockIdx.x * 128 + threadIdx.x;
    const size_t base = (size_t)(b * SS) * DD + (size_t)h * HD;

    float q[64];
    {
        const float* qrow = Q + base + (size_t)qi * DD;
#pragma unroll
        for (int d = 0; d < 64; d += 4) {
            float4 v = *(const float4*)(qrow + d);
            q[d] = v.x; q[d+1] = v.y; q[d+2] = v.z; q[d+3] = v.w;
        }
    }

    float o[64];
#pragma unroll
    for (int d = 0; d < 64; d++) o[d] = 0.0f;
    float m = -1e30f, l = 0.0f;

    const int kend = blockIdx.x * 128 + 128;
    for (int kt = 0; kt < kend; kt += 32) {
#pragma unroll
        for (int i = 0; i < 4; i++) {
            int idx4 = threadIdx.x + i * 128;
            int r = idx4 >> 4;
            int c = (idx4 & 15) * 4;
            size_t gaddr = base + (size_t)(kt + r) * DD + c;
            *(float4*)&Ks[r][c] = *(const float4*)(K + gaddr);
            *(float4*)&Vs[r][c] = *(const float4*)(V + gaddr);
        }
        __syncthreads();

        const int jmax = qi - kt + 1;
        float sv[32];
        float tmax = -1e30f;
#pragma unroll
        for (int j = 0; j < 32; j++) {
            float s = 0.0f;
#pragma unroll
            for (int d = 0; d < 64; d++) s += q[d] * Ks[j][d];
            s *= 0.125f;
            sv[j] = (j < jmax) ? s : -1e30f;
            tmax = fmaxf(tmax, sv[j]);
        }
        float nm = fmaxf(m, tmax);
        float corr = __expf(m - nm);
        l *= corr;
#pragma unroll
        for (int d = 0; d < 64; d++) o[d] *= corr;
#pragma unroll
        for (int j = 0; j < 32; j++) {
            float p = __expf(sv[j] - nm);
            l += p;
#pragma unroll
            for (int d = 0; d < 64; d++)
                o[d] += p * Vs[j][d];
        }
        m = nm;
        __syncthreads();
    }

    float inv = 1.0f / l;
    float* orow = O + base + (size_t)qi * DD;
#pragma unroll
    for (int d = 0; d < 64; d += 4) {
        float4 v;
        v.x = o[d] * inv; v.y = o[d+1] * inv;
        v.z = o[d+2] * inv; v.w = o[d+3] * inv;
        *(float4*)(orow + d) = v;
    }
}

// ---------------- residual add + layernorm (in place on x) ----------------
__global__ void __launch_bounds__(256)
ln_res_kernel(float* __restrict__ x, const float* __restrict__ res,
              const float* __restrict__ g, const float* __restrict__ beta)
{
    __shared__ float red[256];
    const int row = blockIdx.x;
    const int tid = threadIdx.x;
    float* xr = x + (size_t)row * DD;
    const float* rr = res + (size_t)row * DD;

    float y[4];
    float s = 0.0f;
#pragma unroll
    for (int i = 0; i < 4; i++) {
        int d = tid + i * 256;
        y[i] = xr[d] + rr[d];
        s += y[i];
    }
    red[tid] = s; __syncthreads();
    for (int off = 128; off > 0; off >>= 1) {
        if (tid < off) red[tid] += red[tid + off];
        __syncthreads();
    }
    float mu = red[0] * (1.0f / (float)DD);
    __syncthreads();

    float vs = 0.0f;
#pragma unroll
    for (int i = 0; i < 4; i++) {
        float d2 = y[i] - mu;
        vs += d2 * d2;
    }
    red[tid] = vs; __syncthreads();
    for (int off = 128; off > 0; off >>= 1) {
        if (tid < off) red[tid] += red[tid + off];
        __syncthreads();
    }
    float var = red[0] * (1.0f / (float)DD);
    float inv = rsqrtf(var + 1e-5f);

#pragma unroll
    for (int i = 0; i < 4; i++) {
        int d = tid + i * 256;
        xr[d] = (y[i] - mu) * inv * g[d] + beta[d];
    }
}

// ---------------------------------------------------------------------------
extern "C" void kernel_launch(void* const* d_in, const int* in_sizes, int n_in,
                              void* d_out, int out_size)
{
    const int*   tokens = (const int*)  d_in[0];
    const float* emb    = (const float*)d_in[1];
    const float* qw     = (const float*)d_in[2];
    const float* qb     = (const float*)d_in[3];
    const float* kw     = (const float*)d_in[4];
    const float* kb     = (const float*)d_in[5];
    const float* vw     = (const float*)d_in[6];
    const float* vb     = (const float*)d_in[7];
    const float* ow     = (const float*)d_in[8];
    const float* ob     = (const float*)d_in[9];
    const float* ln_g   = (const float*)d_in[10];
    const float* ln_b   = (const float*)d_in[11];
    const float* out_w  = (const float*)d_in[12];
    const float* out_b  = (const float*)d_in[13];
    float* logits = (float*)d_out;

    float *x, *q, *k, *v, *ctx, *attn;
    cudaGetSymbolAddress((void**)&x,    g_x);
    cudaGetSymbolAddress((void**)&q,    g_q);
    cudaGetSymbolAddress((void**)&k,    g_k);
    cudaGetSymbolAddress((void**)&v,    g_v);
    cudaGetSymbolAddress((void**)&ctx,  g_ctx);
    cudaGetSymbolAddress((void**)&attn, g_attn);

    cudaFuncSetAttribute(gemm_mma,     cudaFuncAttributeMaxDynamicSharedMemorySize, GEMM_SMEM_BYTES);
    cudaFuncSetAttribute(gemm_mma_qkv, cudaFuncAttributeMaxDynamicSharedMemorySize, GEMM_SMEM_BYTES);
    cudaFuncSetAttribute(gemm_big,     cudaFuncAttributeMaxDynamicSharedMemorySize, GEMM_BIG_SMEM_BYTES);

    embed_kernel<<<NROW, 256>>>(tokens, emb, x);

    dim3 gqkv(NROW / 128, DD / 128, 3);   // (16, 8, 3)
    dim3 gproj(NROW / 128, DD / 128);     // (16, 8)
    dim3 gattn(SS / 128, HH, BB);

    for (int l = 0; l < LL; l++) {
        size_t wo = (size_t)l * DD * DD;
        size_t bo = (size_t)l * DD;
        gemm_mma_qkv<<<gqkv, 256, GEMM_SMEM_BYTES>>>(x, qw + wo, kw + wo, vw + wo,
                                                     qb + bo, kb + bo, vb + bo, q, k, v);
        attn_kernel<<<gattn, 128>>>(q, k, v, ctx);
        gemm_mma<<<gproj, 256, GEMM_SMEM_BYTES>>>(ctx, ow + wo, ob + bo, attn, NROW, DD, DD);
        ln_res_kernel<<<NROW, 256>>>(x, attn, ln_g + bo, ln_b + bo);
    }

    // final logits: [2048,1024] @ [1024,32000] + bias, 128x256 tiles
    dim3 gout(NROW / 128, VV / 256);      // (16, 125)
    gemm_big<<<gout, 256, GEMM_BIG_SMEM_BYTES>>>(x, out_w, out_b, logits, NROW, VV, DD);
}

// round 8
// speedup vs baseline: 1.5517x; 1.5517x over previous
#include <cuda_runtime.h>
#include <cstdint>
#include <math.h>

#define BB 2
#define SS 1024
#define DD 1024
#define HH 16
#define HD 64
#define LL 4
#define VV 32000
#define NROW (BB * SS)   // 2048
#define NT_OUT (VV / 128)   // 250 N-tiles for logits
#define MT_A   (NROW / 128) // 16 M-tiles
#define KC_D   (DD / 32)    // 32 K-chunks

// ---------------- scratch (static device globals; no allocs allowed) --------
__device__ float g_x[NROW * DD];
__device__ float g_q[NROW * DD];
__device__ float g_k[NROW * DD];
__device__ float g_v[NROW * DD];
__device__ float g_ctx[NROW * DD];
__device__ float g_attn[NROW * DD];
// fragment-major prelayout buffers
__device__ float g_afrag[MT_A * KC_D * 4096];          // 8 MB
__device__ float g_wfrag[(size_t)NT_OUT * KC_D * 4096];// 131 MB

__device__ __forceinline__ float tf32r(float x) {
    float r; asm("cvt.rna.tf32.f32 %0, %1;" : "=f"(r) : "f"(x)); return r;
}

// =================== tf32 mma.sync GEMM, fragment-major smem ================
// (per-layer kernel: CTA 128x128, BK=32, 2 stages, warp tile 64x32)

#define GEMM_SMEM_FLOATS 16384
#define GEMM_SMEM_BYTES  (GEMM_SMEM_FLOATS * 4)

__device__ __forceinline__ void gemm_core(
    const float* __restrict__ A, const float* __restrict__ W,
    const float* __restrict__ bias, float* __restrict__ C,
    int M, int N, int K, int bm, int bn, float* sm)
{
    const int t    = threadIdx.x;
    const int lane = t & 31;
    const int wid  = t >> 5;
    const int g    = lane >> 2;
    const int tg   = lane & 3;
    const int wm   = (wid & 1) * 64;
    const int wn   = (wid >> 1) * 32;

    float acc[4][4][4];
#pragma unroll
    for (int mf = 0; mf < 4; mf++)
#pragma unroll
        for (int nf = 0; nf < 4; nf++)
#pragma unroll
            for (int r = 0; r < 4; r++) acc[mf][nf][r] = 0.0f;

    int aBase[4], bBase[4];
#pragma unroll
    for (int i = 0; i < 4; i++) {
        int idx = t + i * 256;
        {
            int row = idx >> 3, c4 = idx & 7;
            int mi = row >> 4, m16 = row & 15;
            int ga = m16 & 7, rA = m16 >> 3;
            int ki = c4 >> 1, khi = c4 & 1;
            aBase[i] = ((mi * 4 + ki) * 32) * 4 + (rA + 2 * khi);
            aBase[i] |= (ga << 24) | (ki << 28);
        }
        {
            int rowk = idx >> 5, c4 = idx & 31;
            int n0 = c4 * 4;
            int ki = rowk >> 3, kk = rowk & 7;
            int tgb = kk & 3, hi = kk >> 2;
            int ni = n0 >> 3, g0 = n0 & 7;
            int swz = ((ni & 3) << 3) ^ (((ni >> 2) & 3) << 1);
            int ln0 = g0 * 4 + tgb;
            bBase[i] = ((ni * 4 + ki) * 32) * 2 + hi;
            bBase[i] |= (ln0 << 20) | (swz << 26);
        }
    }

    const int nkt = K >> 5;

    const float* aPtr[4];
    const float* bPtr[4];
#pragma unroll
    for (int i = 0; i < 4; i++) {
        int idx = t + i * 256;
        aPtr[i] = A + (size_t)(bm + (idx >> 3)) * K + (idx & 7) * 4;
        bPtr[i] = W + (size_t)(idx >> 5) * N + bn + (idx & 31) * 4;
    }

    auto storeA = [&](int s, int i, float4 v) {
        int meta = aBase[i];
        int base = meta & 0xFFFFF;
        int ga   = (meta >> 24) & 7;
        int ki   = (meta >> 28) & 3;
        float* dst = sm + s * 4096;
        float vv[4] = {tf32r(v.x), tf32r(v.y), tf32r(v.z), tf32r(v.w)};
#pragma unroll
        for (int e = 0; e < 4; e++) {
            int lp = (ga * 4 + e) ^ ki;
            dst[base + lp * 4] = vv[e];
        }
    };
    auto storeB = [&](int s, int i, float4 v) {
        int meta = bBase[i];
        int base = meta & 0xFFFFF;
        int ln0  = (meta >> 20) & 63;
        int swz  = (meta >> 26) & 31;
        float* dst = sm + 8192 + s * 4096;
        float vv[4] = {tf32r(v.x), tf32r(v.y), tf32r(v.z), tf32r(v.w)};
#pragma unroll
        for (int e = 0; e < 4; e++) {
            int lp = (ln0 + 4 * e) ^ swz;
            dst[base + lp * 2] = vv[e];
        }
    };

#pragma unroll
    for (int i = 0; i < 4; i++) {
        storeA(0, i, *(const float4*)aPtr[i]);
        storeB(0, i, *(const float4*)bPtr[i]);
    }
    __syncthreads();

    int bswz[4];
#pragma unroll
    for (int nf = 0; nf < 4; nf++) {
        int ni = (wid >> 1) * 4 + nf;
        bswz[nf] = lane ^ ((ni & 3) << 3) ^ (((ni >> 2) & 3) << 1);
    }

    for (int kt = 0; kt < nkt; kt++) {
        const int cur = kt & 1;
        float4 pa[4], pb[4];
        const bool pf = (kt + 1 < nkt);
        if (pf) {
            const size_t ko = (size_t)(kt + 1) << 5;
#pragma unroll
            for (int i = 0; i < 4; i++) {
                pa[i] = *(const float4*)(aPtr[i] + ko);
                pb[i] = *(const float4*)(bPtr[i] + ko * (size_t)N);
            }
        }

        const float* asb = sm + cur * 4096;
        const float* bsb = sm + 8192 + cur * 4096;
#pragma unroll
        for (int ki = 0; ki < 4; ki++) {
            float4 afv[4];
            float2 bfv[4];
#pragma unroll
            for (int mf = 0; mf < 4; mf++) {
                int mi = (wid & 1) * 4 + mf;
                afv[mf] = *(const float4*)(asb + ((mi * 4 + ki) * 32 + (lane ^ ki)) * 4);
            }
#pragma unroll
            for (int nf = 0; nf < 4; nf++) {
                int ni = (wid >> 1) * 4 + nf;
                bfv[nf] = *(const float2*)(bsb + ((ni * 4 + ki) * 32 + bswz[nf]) * 2);
            }
#pragma unroll
            for (int mf = 0; mf < 4; mf++)
#pragma unroll
                for (int nf = 0; nf < 4; nf++) {
                    asm volatile(
                        "mma.sync.aligned.m16n8k8.row.col.f32.tf32.tf32.f32 "
                        "{%0,%1,%2,%3}, {%4,%5,%6,%7}, {%8,%9}, {%0,%1,%2,%3};"
                        : "+f"(acc[mf][nf][0]), "+f"(acc[mf][nf][1]),
                          "+f"(acc[mf][nf][2]), "+f"(acc[mf][nf][3])
                        : "r"(__float_as_uint(afv[mf].x)), "r"(__float_as_uint(afv[mf].y)),
                          "r"(__float_as_uint(afv[mf].z)), "r"(__float_as_uint(afv[mf].w)),
                          "r"(__float_as_uint(bfv[nf].x)), "r"(__float_as_uint(bfv[nf].y)));
                }
        }

        if (pf) {
            const int nxt = 1 - cur;
#pragma unroll
            for (int i = 0; i < 4; i++) {
                storeA(nxt, i, pa[i]);
                storeB(nxt, i, pb[i]);
            }
        }
        __syncthreads();
    }

#pragma unroll
    for (int mf = 0; mf < 4; mf++) {
        const int r0 = bm + wm + mf * 16 + g;
        const int r1 = r0 + 8;
#pragma unroll
        for (int nf = 0; nf < 4; nf++) {
            const int col = bn + wn + nf * 8 + tg * 2;
            const float b0 = bias[col], b1 = bias[col + 1];
            float2 v0 = make_float2(acc[mf][nf][0] + b0, acc[mf][nf][1] + b1);
            float2 v1 = make_float2(acc[mf][nf][2] + b0, acc[mf][nf][3] + b1);
            *(float2*)(C + (size_t)r0 * N + col) = v0;
            *(float2*)(C + (size_t)r1 * N + col) = v1;
        }
    }
}

__global__ void __launch_bounds__(256)
gemm_mma(const float* __restrict__ A, const float* __restrict__ W,
         const float* __restrict__ bias, float* __restrict__ C,
         int M, int N, int K)
{
    extern __shared__ float sm[];
    gemm_core(A, W, bias, C, M, N, K, blockIdx.x * 128, blockIdx.y * 128, sm);
}

__global__ void __launch_bounds__(256)
gemm_mma_qkv(const float* __restrict__ A,
             const float* __restrict__ qw, const float* __restrict__ kw,
             const float* __restrict__ vw,
             const float* __restrict__ qb, const float* __restrict__ kb,
             const float* __restrict__ vb,
             float* __restrict__ qo, float* __restrict__ ko, float* __restrict__ vo)
{
    extern __shared__ float sm[];
    const float* W    = (blockIdx.z == 0) ? qw : (blockIdx.z == 1) ? kw : vw;
    const float* bias = (blockIdx.z == 0) ? qb : (blockIdx.z == 1) ? kb : vb;
    float*       C    = (blockIdx.z == 0) ? qo : (blockIdx.z == 1) ? ko : vo;
    gemm_core(A, W, bias, C, NROW, DD, DD, blockIdx.x * 128, blockIdx.y * 128, sm);
}

// =================== prelayout kernels (scatter ONCE into gmem) =============
// A chunk (mt, kc): 128 rows x 32 k -> 4096 floats, layout identical to smem
// stage of gemm_core (aBase/storeA formulas).
__global__ void __launch_bounds__(256)
prelayout_A(const float* __restrict__ A, float* __restrict__ out, int K)
{
    const int kc = blockIdx.x;      // K-chunk
    const int mt = blockIdx.y;      // M-tile
    const int t  = threadIdx.x;
    float* dst = out + ((size_t)mt * gridDim.x + kc) * 4096;
#pragma unroll
    for (int i = 0; i < 4; i++) {
        int idx = t + i * 256;
        int row = idx >> 3, c4 = idx & 7;
        int mi = row >> 4, m16 = row & 15;
        int ga = m16 & 7, rA = m16 >> 3;
        int ki = c4 >> 1, khi = c4 & 1;
        int base = ((mi * 4 + ki) * 32) * 4 + (rA + 2 * khi);
        float4 v = *(const float4*)(A + (size_t)(mt * 128 + row) * K + kc * 32 + c4 * 4);
        float vv[4] = {tf32r(v.x), tf32r(v.y), tf32r(v.z), tf32r(v.w)};
#pragma unroll
        for (int e = 0; e < 4; e++) {
            int lp = (ga * 4 + e) ^ ki;
            dst[base + lp * 4] = vv[e];
        }
    }
}

// W chunk (nt, kc): 32 k x 128 n -> 4096 floats, layout identical to smem B
// stage of gemm_core (bBase/storeB formulas).
__global__ void __launch_bounds__(256)
prelayout_W(const float* __restrict__ W, float* __restrict__ out, int N)
{
    const int kc = blockIdx.x;
    const int nt = blockIdx.y;
    const int t  = threadIdx.x;
    float* dst = out + ((size_t)nt * gridDim.x + kc) * 4096;
#pragma unroll
    for (int i = 0; i < 4; i++) {
        int idx = t + i * 256;
        int rowk = idx >> 5, c4 = idx & 31;
        int n0 = c4 * 4;
        int ki = rowk >> 3, kk = rowk & 7;
        int tgb = kk & 3, hi = kk >> 2;
        int ni = n0 >> 3, g0 = n0 & 7;
        int swz = ((ni & 3) << 3) ^ (((ni >> 2) & 3) << 1);
        int ln0 = g0 * 4 + tgb;
        int base = ((ni * 4 + ki) * 32) * 2 + hi;
        float4 v = *(const float4*)(W + (size_t)(kc * 32 + rowk) * N + nt * 128 + n0);
        float vv[4] = {tf32r(v.x), tf32r(v.y), tf32r(v.z), tf32r(v.w)};
#pragma unroll
        for (int e = 0; e < 4; e++) {
            int lp = (ln0 + 4 * e) ^ swz;
            dst[base + lp * 2] = vv[e];
        }
    }
}

// =================== GEMM on prelaid fragment-major operands ================
// afrag: [MT][KC][4096], wfrag: [NT][KC][4096]. Inner loop = pure copy + MMA.
__global__ void __launch_bounds__(256)
gemm_pre(const float* __restrict__ afrag, const float* __restrict__ wfrag,
         const float* __restrict__ bias, float* __restrict__ C,
         int N, int nkc)
{
    extern __shared__ float sm[];
    const int t    = threadIdx.x;
    const int lane = t & 31;
    const int wid  = t >> 5;
    const int g    = lane >> 2;
    const int tg   = lane & 3;
    const int mt   = blockIdx.x;
    const int nt   = blockIdx.y;
    const int wm   = (wid & 1) * 64;
    const int wn   = (wid >> 1) * 32;

    float acc[4][4][4];
#pragma unroll
    for (int mf = 0; mf < 4; mf++)
#pragma unroll
        for (int nf = 0; nf < 4; nf++)
#pragma unroll
            for (int r = 0; r < 4; r++) acc[mf][nf][r] = 0.0f;

    const float* aSrc = afrag + (size_t)mt * nkc * 4096;
    const float* bSrc = wfrag + (size_t)nt * nkc * 4096;

    // stage 0 copy (verbatim)
#pragma unroll
    for (int i = 0; i < 4; i++) {
        int o4 = (t + i * 256) * 4;
        *(float4*)(sm + o4)        = *(const float4*)(aSrc + o4);
        *(float4*)(sm + 8192 + o4) = *(const float4*)(bSrc + o4);
    }
    __syncthreads();

    int bswz[4];
#pragma unroll
    for (int nf = 0; nf < 4; nf++) {
        int ni = (wid >> 1) * 4 + nf;
        bswz[nf] = lane ^ ((ni & 3) << 3) ^ (((ni >> 2) & 3) << 1);
    }

    for (int kt = 0; kt < nkc; kt++) {
        const int cur = kt & 1;
        float4 pa[4], pb[4];
        const bool pf = (kt + 1 < nkc);
        if (pf) {
            const float* an = aSrc + (size_t)(kt + 1) * 4096;
            const float* bn = bSrc + (size_t)(kt + 1) * 4096;
#pragma unroll
            for (int i = 0; i < 4; i++) {
                int o4 = (t + i * 256) * 4;
                pa[i] = *(const float4*)(an + o4);
                pb[i] = *(const float4*)(bn + o4);
            }
        }

        const float* asb = sm + cur * 4096;
        const float* bsb = sm + 8192 + cur * 4096;
#pragma unroll
        for (int ki = 0; ki < 4; ki++) {
            float4 afv[4];
            float2 bfv[4];
#pragma unroll
            for (int mf = 0; mf < 4; mf++) {
                int mi = (wid & 1) * 4 + mf;
                afv[mf] = *(const float4*)(asb + ((mi * 4 + ki) * 32 + (lane ^ ki)) * 4);
            }
#pragma unroll
            for (int nf = 0; nf < 4; nf++) {
                int ni = (wid >> 1) * 4 + nf;
                bfv[nf] = *(const float2*)(bsb + ((ni * 4 + ki) * 32 + bswz[nf]) * 2);
            }
#pragma unroll
            for (int mf = 0; mf < 4; mf++)
#pragma unroll
                for (int nf = 0; nf < 4; nf++) {
                    asm volatile(
                        "mma.sync.aligned.m16n8k8.row.col.f32.tf32.tf32.f32 "
                        "{%0,%1,%2,%3}, {%4,%5,%6,%7}, {%8,%9}, {%0,%1,%2,%3};"
                        : "+f"(acc[mf][nf][0]), "+f"(acc[mf][nf][1]),
                          "+f"(acc[mf][nf][2]), "+f"(acc[mf][nf][3])
                        : "r"(__float_as_uint(afv[mf].x)), "r"(__float_as_uint(afv[mf].y)),
                          "r"(__float_as_uint(afv[mf].z)), "r"(__float_as_uint(afv[mf].w)),
                          "r"(__float_as_uint(bfv[nf].x)), "r"(__float_as_uint(bfv[nf].y)));
                }
        }

        if (pf) {
            const int nxt = 1 - cur;
#pragma unroll
            for (int i = 0; i < 4; i++) {
                int o4 = (t + i * 256) * 4;
                *(float4*)(sm + nxt * 4096 + o4)        = pa[i];
                *(float4*)(sm + 8192 + nxt * 4096 + o4) = pb[i];
            }
        }
        __syncthreads();
    }

#pragma unroll
    for (int mf = 0; mf < 4; mf++) {
        const int r0 = mt * 128 + wm + mf * 16 + g;
        const int r1 = r0 + 8;
#pragma unroll
        for (int nf = 0; nf < 4; nf++) {
            const int col = nt * 128 + wn + nf * 8 + tg * 2;
            const float b0 = bias[col], b1 = bias[col + 1];
            float2 v0 = make_float2(acc[mf][nf][0] + b0, acc[mf][nf][1] + b1);
            float2 v1 = make_float2(acc[mf][nf][2] + b0, acc[mf][nf][3] + b1);
            *(float2*)(C + (size_t)r0 * N + col) = v0;
            *(float2*)(C + (size_t)r1 * N + col) = v1;
        }
    }
}

// ---------------- embedding + sinusoidal positional encoding ---------------
__global__ void embed_kernel(const int* __restrict__ tokens,
                             const float* __restrict__ emb,
                             float* __restrict__ x)
{
    int row = blockIdx.x;
    int pos = row & (SS - 1);
    int tok = tokens[row];
    const float* e = emb + (size_t)tok * DD;
    float* xr = x + (size_t)row * DD;
    const float c = -logf(10000.0f) / (float)DD;
    for (int d = threadIdx.x; d < DD; d += blockDim.x) {
        int i = d >> 1;
        float ang = (float)pos * expf((float)(2 * i) * c);
        float pe = (d & 1) ? cosf(ang) : sinf(ang);
        xr[d] = e[d] + pe;
    }
}

// ---------------- causal flash attention, tile-level online softmax --------
__global__ void __launch_bounds__(128)
attn_kernel(const float* __restrict__ Q, const float* __restrict__ K,
            const float* __restrict__ V, float* __restrict__ O)
{
    __shared__ float Ks[32][64];
    __shared__ float Vs[32][64];

    const int b = blockIdx.z;
    const int h = blockIdx.y;
    const int qi = blockIdx.x * 128 + threadIdx.x;
    const size_t base = (size_t)(b * SS) * DD + (size_t)h * HD;

    float q[64];
    {
        const float* qrow = Q + base + (size_t)qi * DD;
#pragma unroll
        for (int d = 0; d < 64; d += 4) {
            float4 v = *(const float4*)(qrow + d);
            q[d] = v.x; q[d+1] = v.y; q[d+2] = v.z; q[d+3] = v.w;
        }
    }

    float o[64];
#pragma unroll
    for (int d = 0; d < 64; d++) o[d] = 0.0f;
    float m = -1e30f, l = 0.0f;

    const int kend = blockIdx.x * 128 + 128;
    for (int kt = 0; kt < kend; kt += 32) {
#pragma unroll
        for (int i = 0; i < 4; i++) {
            int idx4 = threadIdx.x + i * 128;
            int r = idx4 >> 4;
            int c = (idx4 & 15) * 4;
            size_t gaddr = base + (size_t)(kt + r) * DD + c;
            *(float4*)&Ks[r][c] = *(const float4*)(K + gaddr);
            *(float4*)&Vs[r][c] = *(const float4*)(V + gaddr);
        }
        __syncthreads();

        const int jmax = qi - kt + 1;
        float sv[32];
        float tmax = -1e30f;
#pragma unroll
        for (int j = 0; j < 32; j++) {
            float s = 0.0f;
#pragma unroll
            for (int d = 0; d < 64; d++) s += q[d] * Ks[j][d];
            s *= 0.125f;
            sv[j] = (j < jmax) ? s : -1e30f;
            tmax = fmaxf(tmax, sv[j]);
        }
        float nm = fmaxf(m, tmax);
        float corr = __expf(m - nm);
        l *= corr;
#pragma unroll
        for (int d = 0; d < 64; d++) o[d] *= corr;
#pragma unroll
        for (int j = 0; j < 32; j++) {
            float p = __expf(sv[j] - nm);
            l += p;
#pragma unroll
            for (int d = 0; d < 64; d++)
                o[d] += p * Vs[j][d];
        }
        m = nm;
        __syncthreads();
    }

    float inv = 1.0f / l;
    float* orow = O + base + (size_t)qi * DD;
#pragma unroll
    for (int d = 0; d < 64; d += 4) {
        float4 v;
        v.x = o[d] * inv; v.y = o[d+1] * inv;
        v.z = o[d+2] * inv; v.w = o[d+3] * inv;
        *(float4*)(orow + d) = v;
    }
}

// ---------------- residual add + layernorm (in place on x) ----------------
__global__ void __launch_bounds__(256)
ln_res_kernel(float* __restrict__ x, const float* __restrict__ res,
              const float* __restrict__ g, const float* __restrict__ beta)
{
    __shared__ float red[256];
    const int row = blockIdx.x;
    const int tid = threadIdx.x;
    float* xr = x + (size_t)row * DD;
    const float* rr = res + (size_t)row * DD;

    float y[4];
    float s = 0.0f;
#pragma unroll
    for (int i = 0; i < 4; i++) {
        int d = tid + i * 256;
        y[i] = xr[d] + rr[d];
        s += y[i];
    }
    red[tid] = s; __syncthreads();
    for (int off = 128; off > 0; off >>= 1) {
        if (tid < off) red[tid] += red[tid + off];
        __syncthreads();
    }
    float mu = red[0] * (1.0f / (float)DD);
    __syncthreads();

    float vs = 0.0f;
#pragma unroll
    for (int i = 0; i < 4; i++) {
        float d2 = y[i] - mu;
        vs += d2 * d2;
    }
    red[tid] = vs; __syncthreads();
    for (int off = 128; off > 0; off >>= 1) {
        if (tid < off) red[tid] += red[tid + off];
        __syncthreads();
    }
    float var = red[0] * (1.0f / (float)DD);
    float inv = rsqrtf(var + 1e-5f);

#pragma unroll
    for (int i = 0; i < 4; i++) {
        int d = tid + i * 256;
        xr[d] = (y[i] - mu) * inv * g[d] + beta[d];
    }
}

// ---------------------------------------------------------------------------
extern "C" void kernel_launch(void* const* d_in, const int* in_sizes, int n_in,
                              void* d_out, int out_size)
{
    const int*   tokens = (const int*)  d_in[0];
    const float* emb    = (const float*)d_in[1];
    const float* qw     = (const float*)d_in[2];
    const float* qb     = (const float*)d_in[3];
    const float* kw     = (const float*)d_in[4];
    const float* kb     = (const float*)d_in[5];
    const float* vw     = (const float*)d_in[6];
    const float* vb     = (const float*)d_in[7];
    const float* ow     = (const float*)d_in[8];
    const float* ob     = (const float*)d_in[9];
    const float* ln_g   = (const float*)d_in[10];
    const float* ln_b   = (const float*)d_in[11];
    const float* out_w  = (const float*)d_in[12];
    const float* out_b  = (const float*)d_in[13];
    float* logits = (float*)d_out;

    float *x, *q, *k, *v, *ctx, *attn, *afrag, *wfrag;
    cudaGetSymbolAddress((void**)&x,     g_x);
    cudaGetSymbolAddress((void**)&q,     g_q);
    cudaGetSymbolAddress((void**)&k,     g_k);
    cudaGetSymbolAddress((void**)&v,     g_v);
    cudaGetSymbolAddress((void**)&ctx,   g_ctx);
    cudaGetSymbolAddress((void**)&attn,  g_attn);
    cudaGetSymbolAddress((void**)&afrag, g_afrag);
    cudaGetSymbolAddress((void**)&wfrag, g_wfrag);

    cudaFuncSetAttribute(gemm_mma,     cudaFuncAttributeMaxDynamicSharedMemorySize, GEMM_SMEM_BYTES);
    cudaFuncSetAttribute(gemm_mma_qkv, cudaFuncAttributeMaxDynamicSharedMemorySize, GEMM_SMEM_BYTES);
    cudaFuncSetAttribute(gemm_pre,     cudaFuncAttributeMaxDynamicSharedMemorySize, GEMM_SMEM_BYTES);

    // prelayout the logits weight once (overlaps nothing it depends on)
    {
        dim3 gw(KC_D, NT_OUT);            // (32, 250)
        prelayout_W<<<gw, 256>>>(out_w, wfrag, VV);
    }

    embed_kernel<<<NROW, 256>>>(tokens, emb, x);

    dim3 gqkv(NROW / 128, DD / 128, 3);   // (16, 8, 3)
    dim3 gproj(NROW / 128, DD / 128);     // (16, 8)
    dim3 gattn(SS / 128, HH, BB);

    for (int l = 0; l < LL; l++) {
        size_t wo = (size_t)l * DD * DD;
        size_t bo = (size_t)l * DD;
        gemm_mma_qkv<<<gqkv, 256, GEMM_SMEM_BYTES>>>(x, qw + wo, kw + wo, vw + wo,
                                                     qb + bo, kb + bo, vb + bo, q, k, v);
        attn_kernel<<<gattn, 128>>>(q, k, v, ctx);
        gemm_mma<<<gproj, 256, GEMM_SMEM_BYTES>>>(ctx, ow + wo, ob + bo, attn, NROW, DD, DD);
        ln_res_kernel<<<NROW, 256>>>(x, attn, ln_g + bo, ln_b + bo);
    }

    // prelayout final activations, then fragment-major logits GEMM
    {
        dim3 ga(KC_D, MT_A);              // (32, 16)
        prelayout_A<<<ga, 256>>>(x, afrag, DD);
        dim3 gout(MT_A, NT_OUT);          // (16, 250)
        gemm_pre<<<gout, 256, GEMM_SMEM_BYTES>>>(afrag, wfrag, out_b, logits, VV, KC_D);
    }
}